// round 12
// baseline (speedup 1.0000x reference)
#include <cuda_runtime.h>
#include <cuda_bf16.h>
#include <cstddef>

// Problem constants
#define BATCH 2
#define SEQ   2048
#define EMB   1024
#define NH    16
#define HD    64
#define INNER (NH * HD)     // 1024
#define MTOT  (BATCH * SEQ) // 4096

// Scratch buffers (allocation-free rule: __device__ globals)
__device__ float g_q[BATCH * NH * SEQ * HD];
__device__ float g_k[BATCH * NH * SEQ * HD];
__device__ float g_v[BATCH * NH * SEQ * HD];
__device__ float g_ctx[BATCH * SEQ * INNER];
// pre-rounded (tf32/RNA) GEMM operands
__device__ float g_qp[MTOT * EMB];
__device__ float g_kp[MTOT * EMB];
__device__ float g_vp[MTOT * EMB];
__device__ float g_wqp[INNER * EMB];
__device__ float g_wkp[INNER * EMB];
__device__ float g_wvp[INNER * EMB];
__device__ float g_wop[EMB * INNER];
__device__ float g_ctxp[MTOT * INNER];

// ---------------------------------------------------------------------------
// tf32 / ldmatrix helpers
// ---------------------------------------------------------------------------
__device__ __forceinline__ unsigned f2tf32(float f) {
    unsigned u;
    asm("cvt.rna.tf32.f32 %0, %1;" : "=r"(u) : "f"(f));
    return u;
}
__device__ __forceinline__ float rna32(float f) {
    return __uint_as_float(f2tf32(f));
}

__device__ __forceinline__ void mma_tf32(
    float& c0, float& c1, float& c2, float& c3,
    unsigned a0, unsigned a1, unsigned a2, unsigned a3,
    unsigned b0, unsigned b1)
{
    asm volatile(
        "mma.sync.aligned.m16n8k8.row.col.f32.tf32.tf32.f32 "
        "{%0,%1,%2,%3}, {%4,%5,%6,%7}, {%8,%9}, {%0,%1,%2,%3};"
        : "+f"(c0), "+f"(c1), "+f"(c2), "+f"(c3)
        : "r"(a0), "r"(a1), "r"(a2), "r"(a3), "r"(b0), "r"(b1));
}

__device__ __forceinline__ void ldsm4(unsigned& r0, unsigned& r1,
                                      unsigned& r2, unsigned& r3, unsigned addr)
{
    asm volatile("ldmatrix.sync.aligned.m8n8.x4.shared.b16 {%0,%1,%2,%3}, [%4];"
                 : "=r"(r0), "=r"(r1), "=r"(r2), "=r"(r3) : "r"(addr));
}

__device__ __forceinline__ void cp16(void* smem, const void* gmem) {
    unsigned a = (unsigned)__cvta_generic_to_shared(smem);
    asm volatile("cp.async.cg.shared.global [%0], [%1], 16;"
                 :: "r"(a), "l"(gmem));
}

// ---------------------------------------------------------------------------
// Prep: RNA-round every element to tf32 (layout unchanged).
// ---------------------------------------------------------------------------
__global__ void prep_kernel(const float* __restrict__ src,
                            float* __restrict__ dst, int n4)
{
    int i = blockIdx.x * blockDim.x + threadIdx.x;
    int stride = gridDim.x * blockDim.x;
    for (; i < n4; i += stride) {
        float4 v = ((const float4*)src)[i];
        ((float4*)dst)[i] = make_float4(rna32(v.x), rna32(v.y),
                                        rna32(v.z), rna32(v.w));
    }
}

// ---------------------------------------------------------------------------
// tf32 NT GEMM v7: pre-rounded inputs, cp.async double-buffer, ldmatrix frags.
// C[m,n] = sum_k X[m,k]*W[n,k]; block 128x128, BK=32, 256 thr, warp 64x32.
// No cvt in-kernel; low regs -> 2 CTAs/SM. grid.z selects operand set.
// ---------------------------------------------------------------------------
#define GS 36
#define GTILE (128 * GS)
#define GEMM7_SMEM (4 * GTILE * 4)   // [As0|Bs0|As1|Bs1] floats = 73728 B

__global__ void __launch_bounds__(256, 2) gemm7_tc_kernel(
    const float* __restrict__ X0, const float* __restrict__ X1,
    const float* __restrict__ X2,
    const float* __restrict__ W0, const float* __restrict__ W1,
    const float* __restrict__ W2,
    float* __restrict__ O0, float* __restrict__ O1, float* __restrict__ O2,
    const float* __restrict__ bias, int mode)
{
    extern __shared__ __align__(16) float sb[];

    const int z = blockIdx.z;
    const float* X = (z == 0) ? X0 : (z == 1) ? X1 : X2;
    const float* W = (z == 0) ? W0 : (z == 1) ? W1 : W2;
    float*       O = (z == 0) ? O0 : (z == 1) ? O1 : O2;

    const int K = EMB;     // 1024
    const int N = INNER;   // 1024

    const int tid  = threadIdx.x;
    const int warp = tid >> 5;
    const int lane = tid & 31;
    const int g    = lane >> 2;
    const int tig  = lane & 3;

    const int row0 = blockIdx.y * 128;
    const int col0 = blockIdx.x * 128;
    const int wm   = (warp >> 2) * 64;   // 0 or 64
    const int wn   = (warp & 3) * 32;    // 0,32,64,96

    // ldmatrix lane addressing
    const int lrow  = lane & 15;
    const int lcol4 = (lane >> 4) << 2;

    // cp.async staging: thread -> (row=tid>>1, 16-float half = (tid&1)*16), x4 chunks
    const int srow = tid >> 1;           // 0..127
    const int scb  = (tid & 1) << 4;     // 0 or 16

    const float* Xg = X + (size_t)(row0 + srow) * K + scb;
    const float* Wg = W + (size_t)(col0 + srow) * K + scb;

    float acc[4][4][4] = {};             // [mi][ni][c]
    const int ktiles = K >> 5;           // 32

    // Prologue: stage tile 0 into buffer 0
    {
        float* ad = sb + srow * GS + scb;
        float* bd = sb + GTILE + srow * GS + scb;
        cp16(ad, Xg);         cp16(ad + 4, Xg + 4);
        cp16(ad + 8, Xg + 8); cp16(ad + 12, Xg + 12);
        cp16(bd, Wg);         cp16(bd + 4, Wg + 4);
        cp16(bd + 8, Wg + 8); cp16(bd + 12, Wg + 12);
        asm volatile("cp.async.commit_group;" ::: "memory");
    }

    for (int t = 0; t < ktiles; t++) {
        const int cur = t & 1;

        __syncthreads();   // all warps done reading buffer cur^1 (tile t-1)

        if (t + 1 < ktiles) {
            const int nxt = cur ^ 1;
            const float* xs = Xg + ((t + 1) << 5);
            const float* ws = Wg + ((t + 1) << 5);
            float* ad = sb + nxt * 2 * GTILE + srow * GS + scb;
            float* bd = sb + nxt * 2 * GTILE + GTILE + srow * GS + scb;
            cp16(ad, xs);         cp16(ad + 4, xs + 4);
            cp16(ad + 8, xs + 8); cp16(ad + 12, xs + 12);
            cp16(bd, ws);         cp16(bd + 4, ws + 4);
            cp16(bd + 8, ws + 8); cp16(bd + 12, ws + 12);
            asm volatile("cp.async.commit_group;" ::: "memory");
            asm volatile("cp.async.wait_group 1;" ::: "memory");
        } else {
            asm volatile("cp.async.wait_group 0;" ::: "memory");
        }
        __syncthreads();   // tile t resident + visible

        const float* Ac = sb + cur * 2 * GTILE;
        const float* Bc = Ac + GTILE;
        const unsigned asb = (unsigned)__cvta_generic_to_shared(Ac);
        const unsigned bsb = (unsigned)__cvta_generic_to_shared(Bc);

        #pragma unroll
        for (int kk = 0; kk < 4; kk++) {
            int k0 = kk << 3;
            unsigned a[4][4], b[2][4];
            #pragma unroll
            for (int mi = 0; mi < 4; mi++) {
                unsigned ad = asb + 4u * ((wm + mi * 16 + lrow) * GS + k0 + lcol4);
                ldsm4(a[mi][0], a[mi][1], a[mi][2], a[mi][3], ad);
            }
            #pragma unroll
            for (int p = 0; p < 2; p++) {
                unsigned bd = bsb + 4u * ((wn + p * 16 + lrow) * GS + k0 + lcol4);
                ldsm4(b[p][0], b[p][1], b[p][2], b[p][3], bd);
            }
            #pragma unroll
            for (int mi = 0; mi < 4; mi++)
                #pragma unroll
                for (int ni = 0; ni < 4; ni++)
                    mma_tf32(acc[mi][ni][0], acc[mi][ni][1],
                             acc[mi][ni][2], acc[mi][ni][3],
                             a[mi][0], a[mi][1], a[mi][2], a[mi][3],
                             b[ni >> 1][ni & 1], b[ni >> 1][(ni & 1) + 2]);
        }
    }

    // Epilogue
    #pragma unroll
    for (int mi = 0; mi < 4; mi++) {
        #pragma unroll
        for (int half = 0; half < 2; half++) {
            int m = row0 + wm + mi * 16 + g + half * 8;
            #pragma unroll
            for (int ni = 0; ni < 4; ni++) {
                int n = col0 + wn + ni * 8 + tig * 2;
                float v0 = acc[mi][ni][half * 2 + 0];
                float v1 = acc[mi][ni][half * 2 + 1];
                if (mode == 0) {
                    v0 += bias[n]; v1 += bias[n + 1];
                    *(float2*)&O[(size_t)m * N + n] = make_float2(v0, v1);
                } else {
                    int b_  = m >> 11;
                    int s_  = m & 2047;
                    int h_  = n >> 6;
                    int d_  = n & 63;
                    size_t base = (((size_t)(b_ * NH + h_)) * SEQ + s_) * HD;
                    *(float2*)&O[base + d_] = make_float2(v0, v1);
                }
            }
        }
    }
}

// ---------------------------------------------------------------------------
// Tensor-core flash attention (tf32 mma) with ldmatrix K / P fragment loads.
// Unchanged from R10.
// ---------------------------------------------------------------------------
#define KST 68
#define VST 72
#define PST 68
#define FLASH_SMEM ((64*KST + 64*VST + 64*PST + 64) * 4)

__global__ void __launch_bounds__(128) flash_tc_kernel(
    const int* __restrict__ pmask,   // (B, SEQ) int32
    const int* __restrict__ fmask,   // scalar int32
    float* __restrict__ ctx)         // (B, SEQ, INNER)
{
    extern __shared__ float sm[];
    float* Ks      = sm;                    // 64*KST
    float* Vs      = Ks + 64 * KST;         // 64*VST
    float* Ps      = Vs + 64 * VST;         // 64*PST
    float* maskadd = Ps + 64 * PST;         // 64

    const int tid  = threadIdx.x;
    const int warp = tid >> 5;
    const int lane = tid & 31;
    const int g    = lane >> 2;
    const int tig  = lane & 3;
    const int lrow  = lane & 15;
    const int lcol4 = (lane >> 4) << 2;

    const unsigned ksb = (unsigned)__cvta_generic_to_shared(Ks);
    const unsigned psb = (unsigned)__cvta_generic_to_shared(Ps);

    const int qt = gridDim.x - 1 - blockIdx.x;  // heavy tiles first
    const int bh = blockIdx.y;
    const int b  = bh >> 4;
    const int h  = bh & 15;
    const int fut = fmask[0];

    const float* Qg = g_q + (size_t)bh * SEQ * HD;
    const float* Kg = g_k + (size_t)bh * SEQ * HD;
    const float* Vg = g_v + (size_t)bh * SEQ * HD;

    // Q a-fragments, scale 1/sqrt(64)=0.125 folded in.
    const int r0 = qt * 64 + warp * 16;
    unsigned qa[8][4];
    #pragma unroll
    for (int kc = 0; kc < 8; kc++) {
        qa[kc][0] = f2tf32(0.125f * Qg[(size_t)(r0 + g)     * HD + kc * 8 + tig]);
        qa[kc][1] = f2tf32(0.125f * Qg[(size_t)(r0 + g + 8) * HD + kc * 8 + tig]);
        qa[kc][2] = f2tf32(0.125f * Qg[(size_t)(r0 + g)     * HD + kc * 8 + tig + 4]);
        qa[kc][3] = f2tf32(0.125f * Qg[(size_t)(r0 + g + 8) * HD + kc * 8 + tig + 4]);
    }

    float om0 = -1e30f, om1 = -1e30f;   // running max (rows g, g+8)
    float ol0 = 0.0f,   ol1 = 0.0f;     // running sum
    float oacc[8][4] = {};              // O c-frags: [d-block][c0..c3]

    const int rowg0 = r0 + g;
    const int rowg1 = r0 + g + 8;

    const int ktmax = fut ? qt : (SEQ / 64 - 1);
    for (int kt = 0; kt <= ktmax; kt++) {
        __syncthreads();   // prior-tile frag reads complete

        // K/V tile -> smem via cp.async (16B each, 8+8 per thread)
        #pragma unroll
        for (int i = 0; i < 8; i++) {
            int idx = tid + i * 128;       // 0..1023
            int r = idx >> 4;
            int c = (idx & 15) << 2;
            cp16(&Ks[r * KST + c], &Kg[(size_t)(kt * 64 + r) * HD + c]);
            cp16(&Vs[r * VST + c], &Vg[(size_t)(kt * 64 + r) * HD + c]);
        }
        if (tid < 64)
            maskadd[tid] = pmask[b * SEQ + kt * 64 + tid] ? 0.0f : -1e30f;
        asm volatile("cp.async.wait_all;" ::: "memory");
        __syncthreads();

        // ---- S = Q K^T : K b-frags via ldmatrix (4 per ks, covering 8 j) ----
        float s[8][4];
        #pragma unroll
        for (int j = 0; j < 8; j++) { s[j][0]=0; s[j][1]=0; s[j][2]=0; s[j][3]=0; }
        #pragma unroll
        for (int ks = 0; ks < 8; ks++) {
            unsigned kb[4][4];
            #pragma unroll
            for (int p = 0; p < 4; p++) {
                unsigned ad = ksb + 4u * ((16 * p + lrow) * KST + 8 * ks + lcol4);
                ldsm4(kb[p][0], kb[p][1], kb[p][2], kb[p][3], ad);
            }
            #pragma unroll
            for (int j = 0; j < 8; j++)
                mma_tf32(s[j][0], s[j][1], s[j][2], s[j][3],
                         qa[ks][0], qa[ks][1], qa[ks][2], qa[ks][3],
                         kb[j >> 1][j & 1], kb[j >> 1][(j & 1) + 2]);
        }

        // ---- masks ----
        const bool diag = fut && (kt == qt);
        #pragma unroll
        for (int j = 0; j < 8; j++) {
            int c0 = 8*j + 2*tig;
            float ma0 = maskadd[c0];
            float ma1 = maskadd[c0 + 1];
            s[j][0] += ma0; s[j][1] += ma1;
            s[j][2] += ma0; s[j][3] += ma1;
            if (diag) {
                int gc0 = kt * 64 + c0;
                if (gc0     > rowg0) s[j][0] = -1e30f;
                if (gc0 + 1 > rowg0) s[j][1] = -1e30f;
                if (gc0     > rowg1) s[j][2] = -1e30f;
                if (gc0 + 1 > rowg1) s[j][3] = -1e30f;
            }
        }

        // ---- online softmax (frag space; reduce over tig via shfl) ----
        float mx0 = -1e30f, mx1 = -1e30f;
        #pragma unroll
        for (int j = 0; j < 8; j++) {
            mx0 = fmaxf(mx0, fmaxf(s[j][0], s[j][1]));
            mx1 = fmaxf(mx1, fmaxf(s[j][2], s[j][3]));
        }
        mx0 = fmaxf(mx0, __shfl_xor_sync(0xffffffffu, mx0, 1));
        mx0 = fmaxf(mx0, __shfl_xor_sync(0xffffffffu, mx0, 2));
        mx1 = fmaxf(mx1, __shfl_xor_sync(0xffffffffu, mx1, 1));
        mx1 = fmaxf(mx1, __shfl_xor_sync(0xffffffffu, mx1, 2));

        float mn0 = fmaxf(om0, mx0);
        float mn1 = fmaxf(om1, mx1);
        float cf0 = __expf(om0 - mn0);
        float cf1 = __expf(om1 - mn1);
        om0 = mn0; om1 = mn1;

        __syncwarp();   // prior-tile Ps a-frag reads complete (warp-private)

        float sum0 = 0.0f, sum1 = 0.0f;
        #pragma unroll
        for (int j = 0; j < 8; j++) {
            float p0 = __expf(s[j][0] - mn0);
            float p1 = __expf(s[j][1] - mn0);
            float p2 = __expf(s[j][2] - mn1);
            float p3 = __expf(s[j][3] - mn1);
            sum0 += p0 + p1;
            sum1 += p2 + p3;
            int cs = 8*j + 2*tig;
            float2 lo = make_float2(__uint_as_float(f2tf32(p0)),
                                    __uint_as_float(f2tf32(p1)));
            float2 hi = make_float2(__uint_as_float(f2tf32(p2)),
                                    __uint_as_float(f2tf32(p3)));
            *(float2*)&Ps[(warp*16 + g)     * PST + cs] = lo;
            *(float2*)&Ps[(warp*16 + g + 8) * PST + cs] = hi;
        }
        sum0 += __shfl_xor_sync(0xffffffffu, sum0, 1);
        sum0 += __shfl_xor_sync(0xffffffffu, sum0, 2);
        sum1 += __shfl_xor_sync(0xffffffffu, sum1, 1);
        sum1 += __shfl_xor_sync(0xffffffffu, sum1, 2);
        ol0 = ol0 * cf0 + sum0;
        ol1 = ol1 * cf1 + sum1;

        // rescale O accumulators
        #pragma unroll
        for (int j = 0; j < 8; j++) {
            oacc[j][0] *= cf0; oacc[j][1] *= cf0;
            oacc[j][2] *= cf1; oacc[j][3] *= cf1;
        }
        __syncwarp();   // P strip visible to whole warp

        // ---- load P a-frags via ldmatrix ----
        unsigned pa[8][4];
        #pragma unroll
        for (int kc = 0; kc < 8; kc++) {
            unsigned ad = psb + 4u * ((warp * 16 + lrow) * PST + 8 * kc + lcol4);
            ldsm4(pa[kc][0], pa[kc][1], pa[kc][2], pa[kc][3], ad);
        }

        // ---- O += P V  (8 d-blocks x 8 k-steps) ----
        #pragma unroll
        for (int j = 0; j < 8; j++) {
            #pragma unroll
            for (int ks = 0; ks < 8; ks++) {
                unsigned b0 = __float_as_uint(Vs[(8*ks + tig)     * VST + 8*j + g]);
                unsigned b1 = __float_as_uint(Vs[(8*ks + tig + 4) * VST + 8*j + g]);
                mma_tf32(oacc[j][0], oacc[j][1], oacc[j][2], oacc[j][3],
                         pa[ks][0], pa[ks][1], pa[ks][2], pa[ks][3], b0, b1);
            }
        }
    }

    // ---- epilogue: normalize + store ----
    float inv0 = (ol0 > 0.0f) ? (1.0f / ol0) : 0.0f;
    float inv1 = (ol1 > 0.0f) ? (1.0f / ol1) : 0.0f;
    #pragma unroll
    for (int j = 0; j < 8; j++) {
        int n = h * HD + 8*j + 2*tig;
        size_t base0 = ((size_t)b * SEQ + rowg0) * INNER + n;
        size_t base1 = ((size_t)b * SEQ + rowg1) * INNER + n;
        *(float2*)&ctx[base0] = make_float2(oacc[j][0] * inv0, oacc[j][1] * inv0);
        *(float2*)&ctx[base1] = make_float2(oacc[j][2] * inv1, oacc[j][3] * inv1);
    }
}

// ---------------------------------------------------------------------------
// Launch
// ---------------------------------------------------------------------------
extern "C" void kernel_launch(void* const* d_in, const int* in_sizes, int n_in,
                              void* d_out, int out_size)
{
    const float* q  = (const float*)d_in[0];
    const float* k  = (const float*)d_in[1];
    const float* v  = (const float*)d_in[2];
    const int*   pm = (const int*)d_in[3];
    const int*   fm = (const int*)d_in[4];
    const float* Wq = (const float*)d_in[5];
    const float* Wk = (const float*)d_in[6];
    const float* Wv = (const float*)d_in[7];
    const float* Wo = (const float*)d_in[8];
    const float* bo = (const float*)d_in[9];
    float* out = (float*)d_out;

    float *gq, *gk, *gv, *gctx;
    float *gqp, *gkp, *gvp, *gwqp, *gwkp, *gwvp, *gwop, *gctxp;
    cudaGetSymbolAddress((void**)&gq,    g_q);
    cudaGetSymbolAddress((void**)&gk,    g_k);
    cudaGetSymbolAddress((void**)&gv,    g_v);
    cudaGetSymbolAddress((void**)&gctx,  g_ctx);
    cudaGetSymbolAddress((void**)&gqp,   g_qp);
    cudaGetSymbolAddress((void**)&gkp,   g_kp);
    cudaGetSymbolAddress((void**)&gvp,   g_vp);
    cudaGetSymbolAddress((void**)&gwqp,  g_wqp);
    cudaGetSymbolAddress((void**)&gwkp,  g_wkp);
    cudaGetSymbolAddress((void**)&gwvp,  g_wvp);
    cudaGetSymbolAddress((void**)&gwop,  g_wop);
    cudaGetSymbolAddress((void**)&gctxp, g_ctxp);

    cudaFuncSetAttribute(gemm7_tc_kernel,
                         cudaFuncAttributeMaxDynamicSharedMemorySize, GEMM7_SMEM);
    cudaFuncSetAttribute(flash_tc_kernel,
                         cudaFuncAttributeMaxDynamicSharedMemorySize, FLASH_SMEM);

    // Pre-round all GEMM operands to tf32 (RNA), layout unchanged
    const int PB = 256, PG = 1024;
    prep_kernel<<<PG, PB>>>(q,  gqp,  MTOT * EMB / 4);
    prep_kernel<<<PG, PB>>>(k,  gkp,  MTOT * EMB / 4);
    prep_kernel<<<PG, PB>>>(v,  gvp,  MTOT * EMB / 4);
    prep_kernel<<<PG, PB>>>(Wq, gwqp, INNER * EMB / 4);
    prep_kernel<<<PG, PB>>>(Wk, gwkp, INNER * EMB / 4);
    prep_kernel<<<PG, PB>>>(Wv, gwvp, INNER * EMB / 4);
    prep_kernel<<<PG, PB>>>(Wo, gwop, EMB * INNER / 4);

    // Fused QKV projections -> (B,H,S,D) layout
    gemm7_tc_kernel<<<dim3(INNER / 128, MTOT / 128, 3), 256, GEMM7_SMEM>>>(
        gqp, gkp, gvp, gwqp, gwkp, gwvp, gq, gk, gv, nullptr, 1);

    // Flash attention (tf32 tensor cores)
    flash_tc_kernel<<<dim3(SEQ / 64, BATCH * NH), 128, FLASH_SMEM>>>(pm, fm, gctx);

    // Round ctx, then output projection + bias
    prep_kernel<<<PG, PB>>>(gctx, gctxp, MTOT * INNER / 4);
    gemm7_tc_kernel<<<dim3(EMB / 128, MTOT / 128, 1), 256, GEMM7_SMEM>>>(
        gctxp, gctxp, gctxp, gwop, gwop, gwop, out, out, out, bo, 0);
}

// round 13
// speedup vs baseline: 1.1873x; 1.1873x over previous
#include <cuda_runtime.h>
#include <cuda_bf16.h>
#include <cstddef>

// Problem constants
#define BATCH 2
#define SEQ   2048
#define EMB   1024
#define NH    16
#define HD    64
#define INNER (NH * HD)     // 1024
#define MTOT  (BATCH * SEQ) // 4096

// Scratch buffers (allocation-free rule: __device__ globals)
__device__ float g_q[BATCH * NH * SEQ * HD];
__device__ float g_k[BATCH * NH * SEQ * HD];
__device__ float g_v[BATCH * NH * SEQ * HD];
__device__ float g_ctx[BATCH * SEQ * INNER];

// ---------------------------------------------------------------------------
// tf32 / ldmatrix helpers
// ---------------------------------------------------------------------------
__device__ __forceinline__ unsigned f2tf32(float f) {
    unsigned u;
    asm("cvt.rna.tf32.f32 %0, %1;" : "=r"(u) : "f"(f));
    return u;
}

__device__ __forceinline__ void mma_tf32(
    float& c0, float& c1, float& c2, float& c3,
    unsigned a0, unsigned a1, unsigned a2, unsigned a3,
    unsigned b0, unsigned b1)
{
    asm volatile(
        "mma.sync.aligned.m16n8k8.row.col.f32.tf32.tf32.f32 "
        "{%0,%1,%2,%3}, {%4,%5,%6,%7}, {%8,%9}, {%0,%1,%2,%3};"
        : "+f"(c0), "+f"(c1), "+f"(c2), "+f"(c3)
        : "r"(a0), "r"(a1), "r"(a2), "r"(a3), "r"(b0), "r"(b1));
}

// ldmatrix x4: four 8x(4xb32) matrices. Lane l supplies the row address for
// matrix l>>3, row l&7. Register m <- matrix m, thread(g,tig) gets (row g, col tig).
__device__ __forceinline__ void ldsm4(unsigned& r0, unsigned& r1,
                                      unsigned& r2, unsigned& r3, unsigned addr)
{
    asm volatile("ldmatrix.sync.aligned.m8n8.x4.shared.b16 {%0,%1,%2,%3}, [%4];"
                 : "=r"(r0), "=r"(r1), "=r"(r2), "=r"(r3) : "r"(addr));
}

__device__ __forceinline__ void cp16(void* smem, const void* gmem) {
    unsigned a = (unsigned)__cvta_generic_to_shared(smem);
    asm volatile("cp.async.cg.shared.global [%0], [%1], 16;"
                 :: "r"(a), "l"(gmem));
}

// ---------------------------------------------------------------------------
// tf32 NT GEMM v6 (unchanged from R10 — best known):
// C[m,n] = sum_k X[m,k] * W[n,k]; block 128x128, BK=32, 256 thr, warp 64x32.
// Register-staged gmem prefetch; cvt.rna at STS; ldmatrix frag loads.
// grid.z selects operand set. mode 1: scatter to (b,h,s,d).
// ---------------------------------------------------------------------------
#define GS 36
__global__ void __launch_bounds__(256) gemm6_tc_kernel(
    const float* __restrict__ X0, const float* __restrict__ X1,
    const float* __restrict__ X2,
    const float* __restrict__ W0, const float* __restrict__ W1,
    const float* __restrict__ W2,
    float* __restrict__ O0, float* __restrict__ O1, float* __restrict__ O2,
    const float* __restrict__ bias, int mode)
{
    __shared__ __align__(16) unsigned As[128 * GS];
    __shared__ __align__(16) unsigned Bs[128 * GS];

    const int z = blockIdx.z;
    const float* X = (z == 0) ? X0 : (z == 1) ? X1 : X2;
    const float* W = (z == 0) ? W0 : (z == 1) ? W1 : W2;
    float*       O = (z == 0) ? O0 : (z == 1) ? O1 : O2;

    const int K = EMB;     // 1024
    const int N = INNER;   // 1024

    const int tid  = threadIdx.x;
    const int warp = tid >> 5;
    const int lane = tid & 31;
    const int g    = lane >> 2;
    const int tig  = lane & 3;

    const int row0 = blockIdx.y * 128;
    const int col0 = blockIdx.x * 128;
    const int wm   = (warp >> 2) * 64;   // 0 or 64
    const int wn   = (warp & 3) * 32;    // 0,32,64,96

    // ldmatrix lane addressing
    const int lrow  = lane & 15;
    const int lcol4 = (lane >> 4) << 2;

    const unsigned asb = (unsigned)__cvta_generic_to_shared(As);
    const unsigned bsb = (unsigned)__cvta_generic_to_shared(Bs);

    // gmem staging: 4 float4 per operand per tile
    const int srow = tid >> 3;          // 0..31 (row step 32)
    const int sc4  = (tid & 7) << 2;    // 0,4,...,28

    float acc[4][4][4] = {};            // [mi][ni][c0..c3]
    float4 xv[4], wv[4];

    const int ktiles = K >> 5;

    // Prologue: load tile 0
    #pragma unroll
    for (int i = 0; i < 4; i++) {
        int r = srow + i * 32;
        xv[i] = *(const float4*)&X[(size_t)(row0 + r) * K + sc4];
        wv[i] = *(const float4*)&W[(size_t)(col0 + r) * K + sc4];
    }

    for (int t = 0; t < ktiles; t++) {
        // store staged tile to smem (with tf32 convert)
        #pragma unroll
        for (int i = 0; i < 4; i++) {
            int r = srow + i * 32;
            unsigned* pa = &As[r * GS + sc4];
            pa[0] = f2tf32(xv[i].x); pa[1] = f2tf32(xv[i].y);
            pa[2] = f2tf32(xv[i].z); pa[3] = f2tf32(xv[i].w);
            unsigned* pb = &Bs[r * GS + sc4];
            pb[0] = f2tf32(wv[i].x); pb[1] = f2tf32(wv[i].y);
            pb[2] = f2tf32(wv[i].z); pb[3] = f2tf32(wv[i].w);
        }
        __syncthreads();

        // prefetch next tile into registers
        if (t + 1 < ktiles) {
            int k0 = (t + 1) << 5;
            #pragma unroll
            for (int i = 0; i < 4; i++) {
                int r = srow + i * 32;
                xv[i] = *(const float4*)&X[(size_t)(row0 + r) * K + k0 + sc4];
                wv[i] = *(const float4*)&W[(size_t)(col0 + r) * K + k0 + sc4];
            }
        }

        // 4 k8-steps of mma; fragments via ldmatrix
        #pragma unroll
        for (int kk = 0; kk < 4; kk++) {
            int k0 = kk << 3;
            unsigned a[4][4], b[2][4];
            #pragma unroll
            for (int mi = 0; mi < 4; mi++) {
                unsigned ad = asb + 4u * ((wm + mi * 16 + lrow) * GS + k0 + lcol4);
                ldsm4(a[mi][0], a[mi][1], a[mi][2], a[mi][3], ad);
            }
            #pragma unroll
            for (int p = 0; p < 2; p++) {
                unsigned bd = bsb + 4u * ((wn + p * 16 + lrow) * GS + k0 + lcol4);
                ldsm4(b[p][0], b[p][1], b[p][2], b[p][3], bd);
            }
            #pragma unroll
            for (int mi = 0; mi < 4; mi++)
                #pragma unroll
                for (int ni = 0; ni < 4; ni++)
                    mma_tf32(acc[mi][ni][0], acc[mi][ni][1],
                             acc[mi][ni][2], acc[mi][ni][3],
                             a[mi][0], a[mi][1], a[mi][2], a[mi][3],
                             b[ni >> 1][ni & 1], b[ni >> 1][(ni & 1) + 2]);
        }
        __syncthreads();
    }

    // Epilogue
    #pragma unroll
    for (int mi = 0; mi < 4; mi++) {
        #pragma unroll
        for (int half = 0; half < 2; half++) {
            int m = row0 + wm + mi * 16 + g + half * 8;
            #pragma unroll
            for (int ni = 0; ni < 4; ni++) {
                int n = col0 + wn + ni * 8 + tig * 2;
                float v0 = acc[mi][ni][half * 2 + 0];
                float v1 = acc[mi][ni][half * 2 + 1];
                if (mode == 0) {
                    v0 += bias[n]; v1 += bias[n + 1];
                    *(float2*)&O[(size_t)m * N + n] = make_float2(v0, v1);
                } else {
                    int b_  = m >> 11;
                    int s_  = m & 2047;
                    int h_  = n >> 6;
                    int d_  = n & 63;
                    size_t base = (((size_t)(b_ * NH + h_)) * SEQ + s_) * HD;
                    *(float2*)&O[base + d_] = make_float2(v0, v1);
                }
            }
        }
    }
}

// ---------------------------------------------------------------------------
// Tensor-core flash attention (tf32 mma), ldmatrix frag loads,
// NOW with double-buffered K/V via cp.async commit groups:
// tile kt+1 streams in while tile kt computes.
// Block: 64 q-rows x one (b,h). 4 warps, 16 q-rows each.
// ---------------------------------------------------------------------------
#define KST 68
#define VST 72
#define PST 68
#define KVW (64 * KST + 64 * VST)                 // one K/V stage, floats
#define FLASH_SMEM ((2 * KVW + 64 * PST + 128) * 4)

__global__ void __launch_bounds__(128) flash_tc_kernel(
    const int* __restrict__ pmask,   // (B, SEQ) int32
    const int* __restrict__ fmask,   // scalar int32
    float* __restrict__ ctx)         // (B, SEQ, INNER)
{
    extern __shared__ float sm[];
    // stages: [Ks0|Vs0][Ks1|Vs1], then Ps, then maskadd[2][64]
    float* Ps      = sm + 2 * KVW;          // 64*PST
    float* maskadd = Ps + 64 * PST;         // 2*64

    const int tid  = threadIdx.x;
    const int warp = tid >> 5;
    const int lane = tid & 31;
    const int g    = lane >> 2;
    const int tig  = lane & 3;
    const int lrow  = lane & 15;
    const int lcol4 = (lane >> 4) << 2;

    const unsigned psb = (unsigned)__cvta_generic_to_shared(Ps);

    const int qt = gridDim.x - 1 - blockIdx.x;  // heavy tiles first
    const int bh = blockIdx.y;
    const int b  = bh >> 4;
    const int h  = bh & 15;
    const int fut = fmask[0];

    const float* Qg = g_q + (size_t)bh * SEQ * HD;
    const float* Kg = g_k + (size_t)bh * SEQ * HD;
    const float* Vg = g_v + (size_t)bh * SEQ * HD;

    // staging coords (8 x cp16 each for K and V)
    const int srow = tid >> 1;            // reuse pattern: idx = tid + i*128
    (void)srow;

    // Q a-fragments, scale 1/sqrt(64)=0.125 folded in.
    const int r0 = qt * 64 + warp * 16;
    unsigned qa[8][4];
    #pragma unroll
    for (int kc = 0; kc < 8; kc++) {
        qa[kc][0] = f2tf32(0.125f * Qg[(size_t)(r0 + g)     * HD + kc * 8 + tig]);
        qa[kc][1] = f2tf32(0.125f * Qg[(size_t)(r0 + g + 8) * HD + kc * 8 + tig]);
        qa[kc][2] = f2tf32(0.125f * Qg[(size_t)(r0 + g)     * HD + kc * 8 + tig + 4]);
        qa[kc][3] = f2tf32(0.125f * Qg[(size_t)(r0 + g + 8) * HD + kc * 8 + tig + 4]);
    }

    float om0 = -1e30f, om1 = -1e30f;   // running max (rows g, g+8)
    float ol0 = 0.0f,   ol1 = 0.0f;     // running sum
    float oacc[8][4] = {};              // O c-frags: [d-block][c0..c3]

    const int rowg0 = r0 + g;
    const int rowg1 = r0 + g + 8;

    const int ktmax = fut ? qt : (SEQ / 64 - 1);

    // ---- prologue: stage tile 0 into stage 0 ----
    {
        float* Ks0 = sm;
        float* Vs0 = sm + 64 * KST;
        #pragma unroll
        for (int i = 0; i < 8; i++) {
            int idx = tid + i * 128;
            int r = idx >> 4;
            int c = (idx & 15) << 2;
            cp16(&Ks0[r * KST + c], &Kg[(size_t)r * HD + c]);
            cp16(&Vs0[r * VST + c], &Vg[(size_t)r * HD + c]);
        }
        if (tid < 64)
            maskadd[tid] = pmask[b * SEQ + tid] ? 0.0f : -1e30f;
        asm volatile("cp.async.commit_group;" ::: "memory");
    }

    for (int kt = 0; kt <= ktmax; kt++) {
        const int cur = kt & 1;

        // prefetch tile kt+1 into the other stage (its readers finished at
        // the end-of-iteration barrier of kt-1)
        if (kt + 1 <= ktmax) {
            const int nxt = cur ^ 1;
            float* Ksn = sm + nxt * KVW;
            float* Vsn = Ksn + 64 * KST;
            #pragma unroll
            for (int i = 0; i < 8; i++) {
                int idx = tid + i * 128;
                int r = idx >> 4;
                int c = (idx & 15) << 2;
                cp16(&Ksn[r * KST + c], &Kg[(size_t)((kt + 1) * 64 + r) * HD + c]);
                cp16(&Vsn[r * VST + c], &Vg[(size_t)((kt + 1) * 64 + r) * HD + c]);
            }
            if (tid < 64)
                maskadd[nxt * 64 + tid] =
                    pmask[b * SEQ + (kt + 1) * 64 + tid] ? 0.0f : -1e30f;
            asm volatile("cp.async.commit_group;" ::: "memory");
            asm volatile("cp.async.wait_group 1;" ::: "memory");
        } else {
            asm volatile("cp.async.wait_group 0;" ::: "memory");
        }
        __syncthreads();   // tile kt resident + visible to all warps

        const float* Ks = sm + cur * KVW;
        const float* Vs = Ks + 64 * KST;
        const float* ma = maskadd + cur * 64;
        const unsigned ksb = (unsigned)__cvta_generic_to_shared(Ks);

        // ---- S = Q K^T : K b-frags via ldmatrix (4 per ks, covering 8 j) ----
        float s[8][4];
        #pragma unroll
        for (int j = 0; j < 8; j++) { s[j][0]=0; s[j][1]=0; s[j][2]=0; s[j][3]=0; }
        #pragma unroll
        for (int ks = 0; ks < 8; ks++) {
            unsigned kb[4][4];
            #pragma unroll
            for (int p = 0; p < 4; p++) {
                unsigned ad = ksb + 4u * ((16 * p + lrow) * KST + 8 * ks + lcol4);
                ldsm4(kb[p][0], kb[p][1], kb[p][2], kb[p][3], ad);
            }
            #pragma unroll
            for (int j = 0; j < 8; j++)
                mma_tf32(s[j][0], s[j][1], s[j][2], s[j][3],
                         qa[ks][0], qa[ks][1], qa[ks][2], qa[ks][3],
                         kb[j >> 1][j & 1], kb[j >> 1][(j & 1) + 2]);
        }

        // ---- masks ----
        const bool diag = fut && (kt == qt);
        #pragma unroll
        for (int j = 0; j < 8; j++) {
            int c0 = 8*j + 2*tig;
            float ma0 = ma[c0];
            float ma1 = ma[c0 + 1];
            s[j][0] += ma0; s[j][1] += ma1;
            s[j][2] += ma0; s[j][3] += ma1;
            if (diag) {
                int gc0 = kt * 64 + c0;
                if (gc0     > rowg0) s[j][0] = -1e30f;
                if (gc0 + 1 > rowg0) s[j][1] = -1e30f;
                if (gc0     > rowg1) s[j][2] = -1e30f;
                if (gc0 + 1 > rowg1) s[j][3] = -1e30f;
            }
        }

        // ---- online softmax (frag space; reduce over tig via shfl) ----
        float mx0 = -1e30f, mx1 = -1e30f;
        #pragma unroll
        for (int j = 0; j < 8; j++) {
            mx0 = fmaxf(mx0, fmaxf(s[j][0], s[j][1]));
            mx1 = fmaxf(mx1, fmaxf(s[j][2], s[j][3]));
        }
        mx0 = fmaxf(mx0, __shfl_xor_sync(0xffffffffu, mx0, 1));
        mx0 = fmaxf(mx0, __shfl_xor_sync(0xffffffffu, mx0, 2));
        mx1 = fmaxf(mx1, __shfl_xor_sync(0xffffffffu, mx1, 1));
        mx1 = fmaxf(mx1, __shfl_xor_sync(0xffffffffu, mx1, 2));

        float mn0 = fmaxf(om0, mx0);
        float mn1 = fmaxf(om1, mx1);
        float cf0 = __expf(om0 - mn0);
        float cf1 = __expf(om1 - mn1);
        om0 = mn0; om1 = mn1;

        __syncwarp();   // prior-tile Ps a-frag reads complete (warp-private)

        float sum0 = 0.0f, sum1 = 0.0f;
        #pragma unroll
        for (int j = 0; j < 8; j++) {
            float p0 = __expf(s[j][0] - mn0);
            float p1 = __expf(s[j][1] - mn0);
            float p2 = __expf(s[j][2] - mn1);
            float p3 = __expf(s[j][3] - mn1);
            sum0 += p0 + p1;
            sum1 += p2 + p3;
            int cs = 8*j + 2*tig;
            float2 lo = make_float2(__uint_as_float(f2tf32(p0)),
                                    __uint_as_float(f2tf32(p1)));
            float2 hi = make_float2(__uint_as_float(f2tf32(p2)),
                                    __uint_as_float(f2tf32(p3)));
            *(float2*)&Ps[(warp*16 + g)     * PST + cs] = lo;
            *(float2*)&Ps[(warp*16 + g + 8) * PST + cs] = hi;
        }
        sum0 += __shfl_xor_sync(0xffffffffu, sum0, 1);
        sum0 += __shfl_xor_sync(0xffffffffu, sum0, 2);
        sum1 += __shfl_xor_sync(0xffffffffu, sum1, 1);
        sum1 += __shfl_xor_sync(0xffffffffu, sum1, 2);
        ol0 = ol0 * cf0 + sum0;
        ol1 = ol1 * cf1 + sum1;

        // rescale O accumulators
        #pragma unroll
        for (int j = 0; j < 8; j++) {
            oacc[j][0] *= cf0; oacc[j][1] *= cf0;
            oacc[j][2] *= cf1; oacc[j][3] *= cf1;
        }
        __syncwarp();   // P strip visible to whole warp

        // ---- load P a-frags via ldmatrix ----
        unsigned pa[8][4];
        #pragma unroll
        for (int kc = 0; kc < 8; kc++) {
            unsigned ad = psb + 4u * ((warp * 16 + lrow) * PST + 8 * kc + lcol4);
            ldsm4(pa[kc][0], pa[kc][1], pa[kc][2], pa[kc][3], ad);
        }

        // ---- O += P V  (8 d-blocks x 8 k-steps) ----
        #pragma unroll
        for (int j = 0; j < 8; j++) {
            #pragma unroll
            for (int ks = 0; ks < 8; ks++) {
                unsigned b0 = __float_as_uint(Vs[(8*ks + tig)     * VST + 8*j + g]);
                unsigned b1 = __float_as_uint(Vs[(8*ks + tig + 4) * VST + 8*j + g]);
                mma_tf32(oacc[j][0], oacc[j][1], oacc[j][2], oacc[j][3],
                         pa[ks][0], pa[ks][1], pa[ks][2], pa[ks][3], b0, b1);
            }
        }

        __syncthreads();   // all warps done reading stage cur (overwritten at kt+2)
    }

    // ---- epilogue: normalize + store ----
    float inv0 = (ol0 > 0.0f) ? (1.0f / ol0) : 0.0f;
    float inv1 = (ol1 > 0.0f) ? (1.0f / ol1) : 0.0f;
    #pragma unroll
    for (int j = 0; j < 8; j++) {
        int n = h * HD + 8*j + 2*tig;
        size_t base0 = ((size_t)b * SEQ + rowg0) * INNER + n;
        size_t base1 = ((size_t)b * SEQ + rowg1) * INNER + n;
        *(float2*)&ctx[base0] = make_float2(oacc[j][0] * inv0, oacc[j][1] * inv0);
        *(float2*)&ctx[base1] = make_float2(oacc[j][2] * inv1, oacc[j][3] * inv1);
    }
}

// ---------------------------------------------------------------------------
// Launch
// ---------------------------------------------------------------------------
extern "C" void kernel_launch(void* const* d_in, const int* in_sizes, int n_in,
                              void* d_out, int out_size)
{
    const float* q  = (const float*)d_in[0];
    const float* k  = (const float*)d_in[1];
    const float* v  = (const float*)d_in[2];
    const int*   pm = (const int*)d_in[3];
    const int*   fm = (const int*)d_in[4];
    const float* Wq = (const float*)d_in[5];
    const float* Wk = (const float*)d_in[6];
    const float* Wv = (const float*)d_in[7];
    const float* Wo = (const float*)d_in[8];
    const float* bo = (const float*)d_in[9];
    float* out = (float*)d_out;

    float *gq, *gk, *gv, *gctx;
    cudaGetSymbolAddress((void**)&gq,   g_q);
    cudaGetSymbolAddress((void**)&gk,   g_k);
    cudaGetSymbolAddress((void**)&gv,   g_v);
    cudaGetSymbolAddress((void**)&gctx, g_ctx);

    cudaFuncSetAttribute(flash_tc_kernel,
                         cudaFuncAttributeMaxDynamicSharedMemorySize, FLASH_SMEM);

    dim3 gblk(256);

    // Fused QKV projections -> (B,H,S,D) layout
    gemm6_tc_kernel<<<dim3(INNER / 128, MTOT / 128, 3), gblk>>>(
        q, k, v, Wq, Wk, Wv, gq, gk, gv, nullptr, 1);

    // Flash attention (tf32 tensor cores, double-buffered K/V)
    flash_tc_kernel<<<dim3(SEQ / 64, BATCH * NH), 128, FLASH_SMEM>>>(pm, fm, gctx);

    // Output projection + bias
    gemm6_tc_kernel<<<dim3(EMB / 128, MTOT / 128, 1), gblk>>>(
        gctx, gctx, gctx, Wo, Wo, Wo, out, out, out, bo, 0);
}

// round 15
// speedup vs baseline: 1.9669x; 1.6566x over previous
#include <cuda_runtime.h>
#include <cuda_fp16.h>
#include <cstddef>

// Problem constants
#define BATCH 2
#define SEQ   2048
#define EMB   1024
#define NH    16
#define HD    64
#define INNER (NH * HD)     // 1024
#define MTOT  (BATCH * SEQ) // 4096

// Scratch buffers (allocation-free rule: __device__ globals)
// q/k/v stored fp16 (rounded once at GEMM epilogue); ctx fp32.
__device__ __half g_q[BATCH * NH * SEQ * HD];
__device__ __half g_k[BATCH * NH * SEQ * HD];
__device__ __half g_v[BATCH * NH * SEQ * HD];
__device__ float  g_ctx[BATCH * SEQ * INNER];

// ---------------------------------------------------------------------------
// fp16 mma / ldmatrix helpers
// ---------------------------------------------------------------------------
__device__ __forceinline__ unsigned h2u(__half2 h) {
    return *(unsigned*)&h;
}

__device__ __forceinline__ void mma_f16(
    float& c0, float& c1, float& c2, float& c3,
    unsigned a0, unsigned a1, unsigned a2, unsigned a3,
    unsigned b0, unsigned b1)
{
    asm volatile(
        "mma.sync.aligned.m16n8k16.row.col.f32.f16.f16.f32 "
        "{%0,%1,%2,%3}, {%4,%5,%6,%7}, {%8,%9}, {%0,%1,%2,%3};"
        : "+f"(c0), "+f"(c1), "+f"(c2), "+f"(c3)
        : "r"(a0), "r"(a1), "r"(a2), "r"(a3), "r"(b0), "r"(b1));
}

__device__ __forceinline__ void ldsm4(unsigned& r0, unsigned& r1,
                                      unsigned& r2, unsigned& r3, unsigned addr)
{
    asm volatile("ldmatrix.sync.aligned.m8n8.x4.shared.b16 {%0,%1,%2,%3}, [%4];"
                 : "=r"(r0), "=r"(r1), "=r"(r2), "=r"(r3) : "r"(addr));
}

__device__ __forceinline__ void ldsm4t(unsigned& r0, unsigned& r1,
                                       unsigned& r2, unsigned& r3, unsigned addr)
{
    asm volatile("ldmatrix.sync.aligned.m8n8.x4.trans.shared.b16 {%0,%1,%2,%3}, [%4];"
                 : "=r"(r0), "=r"(r1), "=r"(r2), "=r"(r3) : "r"(addr));
}

__device__ __forceinline__ void cp16(void* smem, const void* gmem) {
    unsigned a = (unsigned)__cvta_generic_to_shared(smem);
    asm volatile("cp.async.cg.shared.global [%0], [%1], 16;"
                 :: "r"(a), "l"(gmem));
}

// ---------------------------------------------------------------------------
// fp16 NT GEMM (R10 structure): C[m,n] = sum_k X[m,k] * W[n,k]
// Block 128x128, BK=32, 256 thr, warp 64x32. fp32 gmem in, convert to half2
// at prefetch; ldmatrix b16 frag loads; m16n8k16 fp16 mma, fp32 accum.
// grid.z selects operand set. mode 1: scatter fp16 to (b,h,s,d); mode 0:
// fp32 out + bias.
// Smem row stride 40 halfs (80B): ldsm rows r*80>>4 = 5r mod 8 -> perm, CF.
// ---------------------------------------------------------------------------
#define GSH 40
__global__ void __launch_bounds__(256) gemm8_tc_kernel(
    const float* __restrict__ X0, const float* __restrict__ X1,
    const float* __restrict__ X2,
    const float* __restrict__ W0, const float* __restrict__ W1,
    const float* __restrict__ W2,
    void* __restrict__ O0, void* __restrict__ O1, void* __restrict__ O2,
    const float* __restrict__ bias, int mode)
{
    __shared__ __align__(16) __half As[128 * GSH];
    __shared__ __align__(16) __half Bs[128 * GSH];

    const int z = blockIdx.z;
    const float* X = (z == 0) ? X0 : (z == 1) ? X1 : X2;
    const float* W = (z == 0) ? W0 : (z == 1) ? W1 : W2;
    void*        O = (z == 0) ? O0 : (z == 1) ? O1 : O2;

    const int K = EMB;     // 1024
    const int N = INNER;   // 1024

    const int tid  = threadIdx.x;
    const int warp = tid >> 5;
    const int lane = tid & 31;
    const int g    = lane >> 2;
    const int tig  = lane & 3;

    const int row0 = blockIdx.y * 128;
    const int col0 = blockIdx.x * 128;
    const int wm   = (warp >> 2) * 64;   // 0 or 64
    const int wn   = (warp & 3) * 32;    // 0,32,64,96

    const int lrow  = lane & 15;
    const int lhi16 = (lane >> 4) << 4;  // byte offset 0/16 within k16

    const unsigned asb = (unsigned)__cvta_generic_to_shared(As);
    const unsigned bsb = (unsigned)__cvta_generic_to_shared(Bs);

    // gmem staging: 4 float4 per operand per tile, converted to half2 pairs
    const int srow = tid >> 3;          // 0..31 (row step 32)
    const int sc4  = (tid & 7) << 2;    // k col 0,4,...,28

    float acc[4][4][4] = {};            // [mi][ni][c0..c3]
    uint2 xh[4], wh[4];                 // staged half2 pairs

    const int ktiles = K >> 5;

    // Prologue: load+convert tile 0
    #pragma unroll
    for (int i = 0; i < 4; i++) {
        int r = srow + i * 32;
        float4 xv = *(const float4*)&X[(size_t)(row0 + r) * K + sc4];
        float4 wv = *(const float4*)&W[(size_t)(col0 + r) * K + sc4];
        xh[i] = make_uint2(h2u(__floats2half2_rn(xv.x, xv.y)),
                           h2u(__floats2half2_rn(xv.z, xv.w)));
        wh[i] = make_uint2(h2u(__floats2half2_rn(wv.x, wv.y)),
                           h2u(__floats2half2_rn(wv.z, wv.w)));
    }

    for (int t = 0; t < ktiles; t++) {
        // store staged tile to smem
        #pragma unroll
        for (int i = 0; i < 4; i++) {
            int r = srow + i * 32;
            *(uint2*)&As[r * GSH + sc4] = xh[i];
            *(uint2*)&Bs[r * GSH + sc4] = wh[i];
        }
        __syncthreads();

        // prefetch+convert next tile
        if (t + 1 < ktiles) {
            int k0 = (t + 1) << 5;
            #pragma unroll
            for (int i = 0; i < 4; i++) {
                int r = srow + i * 32;
                float4 xv = *(const float4*)&X[(size_t)(row0 + r) * K + k0 + sc4];
                float4 wv = *(const float4*)&W[(size_t)(col0 + r) * K + k0 + sc4];
                xh[i] = make_uint2(h2u(__floats2half2_rn(xv.x, xv.y)),
                                   h2u(__floats2half2_rn(xv.z, xv.w)));
                wh[i] = make_uint2(h2u(__floats2half2_rn(wv.x, wv.y)),
                                   h2u(__floats2half2_rn(wv.z, wv.w)));
            }
        }

        // 2 k16-steps of mma; fragments via ldmatrix b16
        #pragma unroll
        for (int kk = 0; kk < 2; kk++) {
            unsigned a[4][4], b[2][4];
            #pragma unroll
            for (int mi = 0; mi < 4; mi++) {
                unsigned ad = asb + (wm + mi * 16 + lrow) * (GSH * 2)
                            + kk * 32 + lhi16;
                ldsm4(a[mi][0], a[mi][1], a[mi][2], a[mi][3], ad);
            }
            #pragma unroll
            for (int p = 0; p < 2; p++) {
                unsigned bd = bsb + (wn + p * 16 + lrow) * (GSH * 2)
                            + kk * 32 + lhi16;
                ldsm4(b[p][0], b[p][1], b[p][2], b[p][3], bd);
            }
            #pragma unroll
            for (int mi = 0; mi < 4; mi++)
                #pragma unroll
                for (int ni = 0; ni < 4; ni++)
                    mma_f16(acc[mi][ni][0], acc[mi][ni][1],
                            acc[mi][ni][2], acc[mi][ni][3],
                            a[mi][0], a[mi][1], a[mi][2], a[mi][3],
                            b[ni >> 1][ni & 1], b[ni >> 1][(ni & 1) + 2]);
        }
        __syncthreads();
    }

    // Epilogue
    #pragma unroll
    for (int mi = 0; mi < 4; mi++) {
        #pragma unroll
        for (int half = 0; half < 2; half++) {
            int m = row0 + wm + mi * 16 + g + half * 8;
            #pragma unroll
            for (int ni = 0; ni < 4; ni++) {
                int n = col0 + wn + ni * 8 + tig * 2;
                float v0 = acc[mi][ni][half * 2 + 0];
                float v1 = acc[mi][ni][half * 2 + 1];
                if (mode == 0) {
                    float* Of = (float*)O;
                    v0 += bias[n]; v1 += bias[n + 1];
                    *(float2*)&Of[(size_t)m * N + n] = make_float2(v0, v1);
                } else {
                    __half* Oh = (__half*)O;
                    int b_  = m >> 11;
                    int s_  = m & 2047;
                    int h_  = n >> 6;
                    int d_  = n & 63;
                    size_t base = (((size_t)(b_ * NH + h_)) * SEQ + s_) * HD;
                    *(__half2*)&Oh[base + d_] = __floats2half2_rn(v0, v1);
                }
            }
        }
    }
}

// ---------------------------------------------------------------------------
// fp16 tensor-core flash attention (R10 structure, m16n8k16).
// Block: 64 q-rows x one (b,h). 4 warps, 16 q-rows each.
// K/V/P in fp16 smem (stride 72 halfs = 144B -> 9r mod 8 perm, ldsm CF).
// K: non-trans ldsm (QK^T b-frags); V: trans ldsm (PV b-frags);
// P: non-trans ldsm (a-frags). Softmax/masks in fp32 frag space.
// ---------------------------------------------------------------------------
#define FST 72
__global__ void __launch_bounds__(128) flash_f16_kernel(
    const int* __restrict__ pmask,   // (B, SEQ) int32
    const int* __restrict__ fmask,   // scalar int32
    float* __restrict__ ctx)         // (B, SEQ, INNER)
{
    __shared__ __align__(16) __half Ks[64 * FST];
    __shared__ __align__(16) __half Vs[64 * FST];
    __shared__ __align__(16) __half Ps[64 * FST];
    __shared__ float maskadd[64];

    const int tid  = threadIdx.x;
    const int warp = tid >> 5;
    const int lane = tid & 31;
    const int g    = lane >> 2;
    const int tig  = lane & 3;
    const int lrow  = lane & 15;
    const int lhi16 = (lane >> 4) << 4;   // byte 0/16

    const unsigned ksb = (unsigned)__cvta_generic_to_shared(Ks);
    const unsigned vsb = (unsigned)__cvta_generic_to_shared(Vs);
    const unsigned psb = (unsigned)__cvta_generic_to_shared(Ps);

    const int qt = gridDim.x - 1 - blockIdx.x;  // heavy tiles first
    const int bh = blockIdx.y;
    const int b  = bh >> 4;
    const int h  = bh & 15;
    const int fut = fmask[0];

    const __half* Qg = g_q + (size_t)bh * SEQ * HD;
    const __half* Kg = g_k + (size_t)bh * SEQ * HD;
    const __half* Vg = g_v + (size_t)bh * SEQ * HD;

    // Q a-fragments (4 k16-steps over d=64), scale 0.125 folded in (exact).
    const int r0 = qt * 64 + warp * 16;
    const __half2 hs = __float2half2_rn(0.125f);
    unsigned qa[4][4];
    #pragma unroll
    for (int kc = 0; kc < 4; kc++) {
        __half2 v0 = *(const __half2*)&Qg[(size_t)(r0 + g)     * HD + kc*16 + 2*tig];
        __half2 v1 = *(const __half2*)&Qg[(size_t)(r0 + g + 8) * HD + kc*16 + 2*tig];
        __half2 v2 = *(const __half2*)&Qg[(size_t)(r0 + g)     * HD + kc*16 + 8 + 2*tig];
        __half2 v3 = *(const __half2*)&Qg[(size_t)(r0 + g + 8) * HD + kc*16 + 8 + 2*tig];
        qa[kc][0] = h2u(__hmul2(v0, hs));
        qa[kc][1] = h2u(__hmul2(v1, hs));
        qa[kc][2] = h2u(__hmul2(v2, hs));
        qa[kc][3] = h2u(__hmul2(v3, hs));
    }

    float om0 = -1e30f, om1 = -1e30f;   // running max (rows g, g+8)
    float ol0 = 0.0f,   ol1 = 0.0f;     // running sum
    float oacc[8][4] = {};              // O c-frags: [d-block][c0..c3]

    const int rowg0 = r0 + g;
    const int rowg1 = r0 + g + 8;

    const int ktmax = fut ? qt : (SEQ / 64 - 1);
    for (int kt = 0; kt <= ktmax; kt++) {
        __syncthreads();   // prior-tile frag reads complete

        // K/V tile -> smem via cp.async (rows of 64 halfs = 128B; 4 x 16B each)
        #pragma unroll
        for (int i = 0; i < 4; i++) {
            int idx = tid + i * 128;       // 0..511
            int r  = idx >> 3;
            int c8 = (idx & 7) << 3;       // half offset 0..56
            cp16(&Ks[r * FST + c8], &Kg[(size_t)(kt * 64 + r) * HD + c8]);
            cp16(&Vs[r * FST + c8], &Vg[(size_t)(kt * 64 + r) * HD + c8]);
        }
        if (tid < 64)
            maskadd[tid] = pmask[b * SEQ + kt * 64 + tid] ? 0.0f : -1e30f;
        asm volatile("cp.async.wait_all;" ::: "memory");
        __syncthreads();

        // ---- S = Q K^T : 4 k16-steps x 8 kv-blocks ----
        float s[8][4];
        #pragma unroll
        for (int j = 0; j < 8; j++) { s[j][0]=0; s[j][1]=0; s[j][2]=0; s[j][3]=0; }
        #pragma unroll
        for (int ks = 0; ks < 4; ks++) {
            unsigned kb[4][4];
            #pragma unroll
            for (int p = 0; p < 4; p++) {
                unsigned ad = ksb + (16 * p + lrow) * (FST * 2) + ks * 32 + lhi16;
                ldsm4(kb[p][0], kb[p][1], kb[p][2], kb[p][3], ad);
            }
            #pragma unroll
            for (int j = 0; j < 8; j++)
                mma_f16(s[j][0], s[j][1], s[j][2], s[j][3],
                        qa[ks][0], qa[ks][1], qa[ks][2], qa[ks][3],
                        kb[j >> 1][j & 1], kb[j >> 1][(j & 1) + 2]);
        }

        // ---- masks ----
        const bool diag = fut && (kt == qt);
        #pragma unroll
        for (int j = 0; j < 8; j++) {
            int c0 = 8*j + 2*tig;
            float ma0 = maskadd[c0];
            float ma1 = maskadd[c0 + 1];
            s[j][0] += ma0; s[j][1] += ma1;
            s[j][2] += ma0; s[j][3] += ma1;
            if (diag) {
                int gc0 = kt * 64 + c0;
                if (gc0     > rowg0) s[j][0] = -1e30f;
                if (gc0 + 1 > rowg0) s[j][1] = -1e30f;
                if (gc0     > rowg1) s[j][2] = -1e30f;
                if (gc0 + 1 > rowg1) s[j][3] = -1e30f;
            }
        }

        // ---- online softmax (frag space; reduce over tig via shfl) ----
        float mx0 = -1e30f, mx1 = -1e30f;
        #pragma unroll
        for (int j = 0; j < 8; j++) {
            mx0 = fmaxf(mx0, fmaxf(s[j][0], s[j][1]));
            mx1 = fmaxf(mx1, fmaxf(s[j][2], s[j][3]));
        }
        mx0 = fmaxf(mx0, __shfl_xor_sync(0xffffffffu, mx0, 1));
        mx0 = fmaxf(mx0, __shfl_xor_sync(0xffffffffu, mx0, 2));
        mx1 = fmaxf(mx1, __shfl_xor_sync(0xffffffffu, mx1, 1));
        mx1 = fmaxf(mx1, __shfl_xor_sync(0xffffffffu, mx1, 2));

        float mn0 = fmaxf(om0, mx0);
        float mn1 = fmaxf(om1, mx1);
        float cf0 = __expf(om0 - mn0);
        float cf1 = __expf(om1 - mn1);
        om0 = mn0; om1 = mn1;

        __syncwarp();   // prior-tile Ps a-frag reads complete (warp-private)

        float sum0 = 0.0f, sum1 = 0.0f;
        #pragma unroll
        for (int j = 0; j < 8; j++) {
            float p0 = __expf(s[j][0] - mn0);
            float p1 = __expf(s[j][1] - mn0);
            float p2 = __expf(s[j][2] - mn1);
            float p3 = __expf(s[j][3] - mn1);
            sum0 += p0 + p1;
            sum1 += p2 + p3;
            int cs = 8*j + 2*tig;
            *(__half2*)&Ps[(warp*16 + g)     * FST + cs] = __floats2half2_rn(p0, p1);
            *(__half2*)&Ps[(warp*16 + g + 8) * FST + cs] = __floats2half2_rn(p2, p3);
        }
        sum0 += __shfl_xor_sync(0xffffffffu, sum0, 1);
        sum0 += __shfl_xor_sync(0xffffffffu, sum0, 2);
        sum1 += __shfl_xor_sync(0xffffffffu, sum1, 1);
        sum1 += __shfl_xor_sync(0xffffffffu, sum1, 2);
        ol0 = ol0 * cf0 + sum0;
        ol1 = ol1 * cf1 + sum1;

        // rescale O accumulators
        #pragma unroll
        for (int j = 0; j < 8; j++) {
            oacc[j][0] *= cf0; oacc[j][1] *= cf0;
            oacc[j][2] *= cf1; oacc[j][3] *= cf1;
        }
        __syncwarp();   // P strip visible to whole warp

        // ---- load P a-frags via ldmatrix (4 k16-steps over kv) ----
        unsigned pa[4][4];
        #pragma unroll
        for (int kc = 0; kc < 4; kc++) {
            unsigned ad = psb + (warp * 16 + lrow) * (FST * 2) + kc * 32 + lhi16;
            ldsm4(pa[kc][0], pa[kc][1], pa[kc][2], pa[kc][3], ad);
        }

        // ---- O += P V : V b-frags via trans ldsm ----
        // vrow: lanes {0-7,16-23} -> kv rows +lane&7; {8-15,24-31} -> +8.
        const int vrow = (lane & 7) + (((lane >> 3) & 1) << 3);
        #pragma unroll
        for (int jj = 0; jj < 4; jj++) {      // d-block pairs (2jj, 2jj+1)
            #pragma unroll
            for (int ks = 0; ks < 4; ks++) {  // kv k16-steps
                unsigned vb[4];
                unsigned ad = vsb + (ks * 16 + vrow) * (FST * 2)
                            + jj * 32 + lhi16;
                ldsm4t(vb[0], vb[1], vb[2], vb[3], ad);
                mma_f16(oacc[2*jj][0], oacc[2*jj][1], oacc[2*jj][2], oacc[2*jj][3],
                        pa[ks][0], pa[ks][1], pa[ks][2], pa[ks][3], vb[0], vb[1]);
                mma_f16(oacc[2*jj+1][0], oacc[2*jj+1][1], oacc[2*jj+1][2], oacc[2*jj+1][3],
                        pa[ks][0], pa[ks][1], pa[ks][2], pa[ks][3], vb[2], vb[3]);
            }
        }
    }

    // ---- epilogue: normalize + store ----
    float inv0 = (ol0 > 0.0f) ? (1.0f / ol0) : 0.0f;
    float inv1 = (ol1 > 0.0f) ? (1.0f / ol1) : 0.0f;
    #pragma unroll
    for (int j = 0; j < 8; j++) {
        int n = h * HD + 8*j + 2*tig;
        size_t base0 = ((size_t)b * SEQ + rowg0) * INNER + n;
        size_t base1 = ((size_t)b * SEQ + rowg1) * INNER + n;
        *(float2*)&ctx[base0] = make_float2(oacc[j][0] * inv0, oacc[j][1] * inv0);
        *(float2*)&ctx[base1] = make_float2(oacc[j][2] * inv1, oacc[j][3] * inv1);
    }
}

// ---------------------------------------------------------------------------
// Launch
// ---------------------------------------------------------------------------
extern "C" void kernel_launch(void* const* d_in, const int* in_sizes, int n_in,
                              void* d_out, int out_size)
{
    const float* q  = (const float*)d_in[0];
    const float* k  = (const float*)d_in[1];
    const float* v  = (const float*)d_in[2];
    const int*   pm = (const int*)d_in[3];
    const int*   fm = (const int*)d_in[4];
    const float* Wq = (const float*)d_in[5];
    const float* Wk = (const float*)d_in[6];
    const float* Wv = (const float*)d_in[7];
    const float* Wo = (const float*)d_in[8];
    const float* bo = (const float*)d_in[9];
    float* out = (float*)d_out;

    void *gq, *gk, *gv;
    float *gctx;
    cudaGetSymbolAddress(&gq, g_q);
    cudaGetSymbolAddress(&gk, g_k);
    cudaGetSymbolAddress(&gv, g_v);
    cudaGetSymbolAddress((void**)&gctx, g_ctx);

    dim3 gblk(256);

    // Fused QKV projections -> (B,H,S,D) fp16 layout
    gemm8_tc_kernel<<<dim3(INNER / 128, MTOT / 128, 3), gblk>>>(
        q, k, v, Wq, Wk, Wv, gq, gk, gv, nullptr, 1);

    // Flash attention (fp16 tensor cores)
    flash_f16_kernel<<<dim3(SEQ / 64, BATCH * NH), 128>>>(pm, fm, gctx);

    // Output projection + bias (fp32 out)
    gemm8_tc_kernel<<<dim3(EMB / 128, MTOT / 128, 1), gblk>>>(
        gctx, gctx, gctx, Wo, Wo, Wo, out, out, out, bo, 0);
}